// round 8
// baseline (speedup 1.0000x reference)
#include <cuda_runtime.h>

namespace {
constexpr int kGroups   = 131072;                 // 64 * 2048
constexpr int kThreads  = 128;
constexpr int kBlocks   = kGroups / kThreads;     // 1024
constexpr float kDT = 0.005f;
}

// [0..kBlocks-1] = per-block sum16, [kBlocks..2*kBlocks-1] = sum32
__device__ double g_partials[2 * kBlocks];
__device__ unsigned int g_sync = 0;

__device__ __forceinline__ void qmul(float aw, float ax, float ay, float az,
                                     float bw, float bx, float by, float bz,
                                     float& w, float& x, float& y, float& z) {
    w = aw*bw - ax*bx - ay*by - az*bz;
    x = aw*bx + ax*bw + ay*bz - az*by;
    y = aw*by - ax*bz + ay*bw + az*bx;
    z = aw*bz + ax*by - ay*bx + az*bw;
}

// exp of phi = kDT * u as unit quaternion, |phi| <= ~0.2: even-poly, branch-free.
__device__ __forceinline__ void exp_quat_dt(float ux, float uy, float uz,
                                            float& w, float& x, float& y, float& z) {
    float n2 = fmaf(ux, ux, fmaf(uy, uy, uz * uz));
    float h2 = (0.25f * kDT * kDT) * n2;                    // (|phi|/2)^2
    w = fmaf(h2, fmaf(h2, (1.0f / 24.0f), -0.5f), 1.0f);
    float s = fmaf(h2, fmaf(h2, (kDT / 240.0f), -(kDT / 12.0f)), 0.5f * kDT);
    x = s * ux; y = s * uy; z = s * uz;                     // s = sin(h)/|u|
}

// atan2(n, w) for n >= 0, w >= 0 (result in [0, pi/2]); ~1e-7 rad
__device__ __forceinline__ float atan2_pos(float n, float w) {
    bool swap = n > w;
    float num = swap ? w : n;
    float den = swap ? n : w;
    float q  = __fdividef(num, den);              // [0, 1]
    float q2 = q * q;
    float p =                     -0.0040540580734172f;
    p = fmaf(p, q2,  0.0218612288251226f);
    p = fmaf(p, q2, -0.0559098861838105f);
    p = fmaf(p, q2,  0.0964200441046623f);
    p = fmaf(p, q2, -0.1390853351676372f);
    p = fmaf(p, q2,  0.1994653599057577f);
    p = fmaf(p, q2, -0.3332985605689738f);
    p = fmaf(p, q2,  0.9999993329093277f);
    float a = p * q;
    return swap ? (1.5707963267948966f - a) : a;
}

// rs = log( R(a)^T R(b) );  returns sum_k SmoothL1(rs_k / HUBER)
__device__ __forceinline__ float log_huber_q(float aw, float ax, float ay, float az,
                                             float bw, float bx, float by, float bz) {
    float w = aw*bw + ax*bx + ay*by + az*bz;      // conj(a) (x) b
    float x = aw*bx - ax*bw - ay*bz + az*by;
    float y = aw*by + ax*bz - ay*bw - az*bx;
    float z = aw*bz - ax*by + ay*bx - az*bw;
    if (w < 0.0f) { w = -w; x = -x; y = -y; z = -z; }
    float n2 = fmaf(x, x, fmaf(y, y, z * z));
    float n  = sqrtf(n2);
    float ang = 2.0f * atan2_pos(n, w);           // [0, pi]
    float coef = __fdividef(ang, fmaxf(n, 1e-20f));
    float r0 = coef * x, r1 = coef * y, r2 = coef * z;

    float sum = 0.0f;
#pragma unroll
    for (int k = 0; k < 3; k++) {
        float r = (k == 0) ? r0 : ((k == 1) ? r1 : r2);
        float xx = r * 200.0f;                    // / HUBER
        float axv = fabsf(xx);
        sum += (axv < 1.0f) ? (0.5f * xx * xx) : (axv - 0.5f);
    }
    return sum;
}

__global__ void __launch_bounds__(kThreads)
dg_loss_kernel(const float* __restrict__ w_hat, const float* __restrict__ dw16,
               float* __restrict__ out) {
    const int m = blockIdx.x * kThreads + threadIdx.x;     // group id, 0..131071
    const int g = m & 2047;                                // group index in row
    const bool mEven = (m & 1) == 0;                       // partner = lane^1

    // ---- issue all 13 loads up front (MLP) ----
    const float4* base = reinterpret_cast<const float4*>(w_hat) + (size_t)m * 12;
    float4 v0  = __ldcs(base + 0),  v1  = __ldcs(base + 1),  v2  = __ldcs(base + 2);
    float4 v3  = __ldcs(base + 3),  v4  = __ldcs(base + 4),  v5  = __ldcs(base + 5);
    float4 v6  = __ldcs(base + 6),  v7  = __ldcs(base + 7),  v8  = __ldcs(base + 8);
    float4 v9  = __ldcs(base + 9),  v10 = __ldcs(base + 10), v11 = __ldcs(base + 11);
    float4 d   = __ldcs(reinterpret_cast<const float4*>(dw16) + (size_t)m * 12);

    // ---- first-order (BCH) composition: sum the 16 rotation vectors ----
    float ux = (((v0.x + v0.w) + (v1.z + v2.y)) + ((v3.x + v3.w) + (v4.z + v5.y)))
             + (((v6.x + v6.w) + (v7.z + v8.y)) + ((v9.x + v9.w) + (v10.z + v11.y)));
    float uy = (((v0.y + v1.x) + (v1.w + v2.z)) + ((v3.y + v4.x) + (v4.w + v5.z)))
             + (((v6.y + v7.x) + (v7.w + v8.z)) + ((v9.y + v10.x) + (v10.w + v11.z)));
    float uz = (((v0.z + v1.y) + (v2.x + v2.w)) + ((v3.z + v4.y) + (v5.x + v5.w)))
             + (((v6.z + v7.y) + (v8.x + v8.w)) + ((v9.z + v10.y) + (v11.x + v11.w)));

    float qw, qx, qy, qz;
    exp_quat_dt(ux, uy, uz, qw, qx, qy, qz);      // qhat for group m

    // ---- ground-truth increment for group m ----
    float pw, px, py, pz;
    {
        float n2 = fmaf(d.x, d.x, fmaf(d.y, d.y, d.z * d.z));
        float th = sqrtf(n2);
        float s, c;
        __sincosf(0.5f * th, &s, &c);
        float k = (th > 1e-7f) ? __fdividef(s, th) : 0.5f;
        pw = c; px = k * d.x; py = k * d.y; pz = k * d.z;
    }

    // ---- 16-level term ----
    float s16 = (g >= 5) ? log_huber_q(qw, qx, qy, qz, pw, px, py, pz) : 0.0f;

    // ---- 32-level: partner group is lane^1 ----
    float qwP = __shfl_xor_sync(0xFFFFFFFFu, qw, 1);
    float qxP = __shfl_xor_sync(0xFFFFFFFFu, qx, 1);
    float qyP = __shfl_xor_sync(0xFFFFFFFFu, qy, 1);
    float qzP = __shfl_xor_sync(0xFFFFFFFFu, qz, 1);
    float pwP = __shfl_xor_sync(0xFFFFFFFFu, pw, 1);
    float pxP = __shfl_xor_sync(0xFFFFFFFFu, px, 1);
    float pyP = __shfl_xor_sync(0xFFFFFFFFu, py, 1);
    float pzP = __shfl_xor_sync(0xFFFFFFFFu, pz, 1);

    float s32 = 0.0f;
    if (mEven && g >= 10) {
        float hw, hx, hy, hz, gw, gx, gy, gz;
        qmul(qw, qx, qy, qz, qwP, qxP, qyP, qzP, hw, hx, hy, hz);   // hat pair
        qmul(pw, px, py, pz, pwP, pxP, pyP, pzP, gw, gx, gy, gz);   // gt pair
        s32 = log_huber_q(hw, hx, hy, hz, gw, gx, gy, gz);
    }

    // ---- deterministic block reduction ----
#pragma unroll
    for (int off = 16; off > 0; off >>= 1) {
        s16 += __shfl_down_sync(0xFFFFFFFFu, s16, off);
        s32 += __shfl_down_sync(0xFFFFFFFFu, s32, off);
    }
    __shared__ float w16[kThreads / 32], w32[kThreads / 32];
    __shared__ double sa[kThreads], sb[kThreads];
    __shared__ bool isLast;
    int lane = threadIdx.x & 31, wid = threadIdx.x >> 5;
    if (lane == 0) { w16[wid] = s16; w32[wid] = s32; }
    __syncthreads();
    if (threadIdx.x == 0) {
        float a = 0.0f, b = 0.0f;
#pragma unroll
        for (int i = 0; i < kThreads / 32; i++) { a += w16[i]; b += w32[i]; }
        g_partials[blockIdx.x] = (double)a;
        g_partials[kBlocks + blockIdx.x] = (double)b;
        __threadfence();
        unsigned prev = atomicAdd(&g_sync, 1u);
        isLast = (prev == (unsigned)(kBlocks - 1));
    }
    __syncthreads();

    // ---- last block: fixed-order final sum => deterministic ----
    if (isLast) {
        __threadfence();
        int tt = threadIdx.x;
        double a = 0.0, b = 0.0;
#pragma unroll
        for (int j = 0; j < kBlocks / kThreads; j++) {
            a += g_partials[tt + j * kThreads];
            b += g_partials[kBlocks + tt + j * kThreads];
        }
        sa[tt] = a; sb[tt] = b;
        __syncthreads();
        for (int off = kThreads / 2; off > 0; off >>= 1) {
            if (tt < off) { sa[tt] += sa[tt + off]; sb[tt] += sb[tt + off]; }
            __syncthreads();
        }
        if (tt == 0) {
            // W * HUBER^2 = 25;  loss16 denom 64*2043*3;  loss32 denom 64*1019*3*4
            double l16 = 25.0 * sa[0] / 392256.0;
            double l32 = 25.0 * sb[0] / 782592.0;
            out[0] = (float)(l16 + l32);
            g_sync = 0;                          // reset for next graph replay
        }
    }
}

extern "C" void kernel_launch(void* const* d_in, const int* in_sizes, int n_in,
                              void* d_out, int out_size) {
    const float* w_hat = (const float*)d_in[0];
    const float* dw16  = (const float*)d_in[1];
    float* out = (float*)d_out;
    dg_loss_kernel<<<kBlocks, kThreads>>>(w_hat, dw16, out);
}

// round 10
// speedup vs baseline: 1.1338x; 1.1338x over previous
#include <cuda_runtime.h>

namespace {
constexpr int kGroups  = 131072;                 // 64 * 2048
constexpr int kThreads = 256;                    // 1 group per thread
constexpr int kBlocks  = kGroups / kThreads;     // 512
constexpr int kVecs    = kThreads * 12;          // 3072 float4 per block tile
constexpr float kDT = 0.005f;
}

// [0..kBlocks-1] = per-block sum16, [kBlocks..2*kBlocks-1] = sum32
__device__ double g_partials[2 * kBlocks];
__device__ unsigned int g_sync = 0;

__device__ __forceinline__ void qmul(float aw, float ax, float ay, float az,
                                     float bw, float bx, float by, float bz,
                                     float& w, float& x, float& y, float& z) {
    w = aw*bw - ax*bx - ay*by - az*bz;
    x = aw*bx + ax*bw + ay*bz - az*by;
    y = aw*by - ax*bz + ay*bw + az*bx;
    z = aw*bz + ax*by - ay*bx + az*bw;
}

// exp of phi = kDT * u as unit quaternion, |phi| <= ~0.2: even-poly, branch-free.
__device__ __forceinline__ void exp_quat_dt(float ux, float uy, float uz,
                                            float& w, float& x, float& y, float& z) {
    float n2 = fmaf(ux, ux, fmaf(uy, uy, uz * uz));
    float h2 = (0.25f * kDT * kDT) * n2;                    // (|phi|/2)^2
    w = fmaf(h2, fmaf(h2, (1.0f / 24.0f), -0.5f), 1.0f);
    float s = fmaf(h2, fmaf(h2, (kDT / 240.0f), -(kDT / 12.0f)), 0.5f * kDT);
    x = s * ux; y = s * uy; z = s * uz;                     // s = sin(h)/|u|
}

// atan2(n, w) for n >= 0, w >= 0 (result in [0, pi/2]); ~1e-7 rad
__device__ __forceinline__ float atan2_pos(float n, float w) {
    bool swap = n > w;
    float num = swap ? w : n;
    float den = swap ? n : w;
    float q  = __fdividef(num, den);              // [0, 1]
    float q2 = q * q;
    float p =                     -0.0040540580734172f;
    p = fmaf(p, q2,  0.0218612288251226f);
    p = fmaf(p, q2, -0.0559098861838105f);
    p = fmaf(p, q2,  0.0964200441046623f);
    p = fmaf(p, q2, -0.1390853351676372f);
    p = fmaf(p, q2,  0.1994653599057577f);
    p = fmaf(p, q2, -0.3332985605689738f);
    p = fmaf(p, q2,  0.9999993329093277f);
    float a = p * q;
    return swap ? (1.5707963267948966f - a) : a;
}

// rs = log( R(a)^T R(b) );  returns sum_k SmoothL1(rs_k / HUBER)
__device__ __forceinline__ float log_huber_q(float aw, float ax, float ay, float az,
                                             float bw, float bx, float by, float bz) {
    float w = aw*bw + ax*bx + ay*by + az*bz;      // conj(a) (x) b
    float x = aw*bx - ax*bw - ay*bz + az*by;
    float y = aw*by + ax*bz - ay*bw - az*bx;
    float z = aw*bz - ax*by + ay*bx - az*bw;
    if (w < 0.0f) { w = -w; x = -x; y = -y; z = -z; }
    float n2 = fmaf(x, x, fmaf(y, y, z * z));
    float n  = sqrtf(n2);
    float ang = 2.0f * atan2_pos(n, w);           // [0, pi]
    float coef = __fdividef(ang, fmaxf(n, 1e-20f));
    float r0 = coef * x, r1 = coef * y, r2 = coef * z;

    float sum = 0.0f;
#pragma unroll
    for (int k = 0; k < 3; k++) {
        float r = (k == 0) ? r0 : ((k == 1) ? r1 : r2);
        float xx = r * 200.0f;                    // / HUBER
        float axv = fabsf(xx);
        sum += (axv < 1.0f) ? (0.5f * xx * xx) : (axv - 0.5f);
    }
    return sum;
}

__global__ void __launch_bounds__(kThreads)
dg_loss_kernel(const float* __restrict__ w_hat, const float* __restrict__ dw16,
               float* __restrict__ out) {
    // component-separated partial sums for the block tile (stride-1 => no ST conflicts;
    // 12-contiguous per group => LDS.128 phase-conflict-free reads)
    __shared__ float s0[kVecs], s1[kVecs], s2[kVecs];

    const int tid = threadIdx.x;
    const int m   = blockIdx.x * kThreads + tid;           // group id, 0..131071
    const int g   = m & 2047;                              // group index in row
    const bool mEven = (m & 1) == 0;                       // partner = lane^1

    // ---- phase 1: fully coalesced w_hat load + per-float4 BCH partials ----
    // float4 j (global) covers floats 4j..4j+3, entirely inside group j/12.
    // component of float (4j+l) is (j + l) mod 3.
    const float4* wbase = reinterpret_cast<const float4*>(w_hat)
                        + (size_t)blockIdx.x * kVecs;
    // dw16 load issued early (latency overlap with phase 1)
    float4 d = __ldcs(reinterpret_cast<const float4*>(dw16) + (size_t)m * 12);

#pragma unroll
    for (int t = 0; t < 12; t++) {
        int jl = t * kThreads + tid;                       // 0..3071
        float4 v = __ldcs(wbase + jl);
        int r = jl % 3;
        float fs = v.x + v.w;                              // comps (r, r+1, r+2, r) -> r gets x+w
        float c0 = (r == 0) ? fs  : ((r == 1) ? v.z : v.y);
        float c1 = (r == 0) ? v.y : ((r == 1) ? fs  : v.z);
        float c2 = (r == 0) ? v.z : ((r == 1) ? v.y : fs );
        s0[jl] = c0; s1[jl] = c1; s2[jl] = c2;
    }
    __syncthreads();

    // ---- phase 2: per-group sum of 12 contiguous partials (3x LDS.128 per comp) ----
    float ux, uy, uz;
    {
        const float4* p0 = reinterpret_cast<const float4*>(s0 + 12 * tid);
        const float4* p1 = reinterpret_cast<const float4*>(s1 + 12 * tid);
        const float4* p2 = reinterpret_cast<const float4*>(s2 + 12 * tid);
        float4 a = p0[0], b = p0[1], c = p0[2];
        ux = ((a.x + a.y) + (a.z + a.w)) + ((b.x + b.y) + (b.z + b.w))
           + ((c.x + c.y) + (c.z + c.w));
        a = p1[0]; b = p1[1]; c = p1[2];
        uy = ((a.x + a.y) + (a.z + a.w)) + ((b.x + b.y) + (b.z + b.w))
           + ((c.x + c.y) + (c.z + c.w));
        a = p2[0]; b = p2[1]; c = p2[2];
        uz = ((a.x + a.y) + (a.z + a.w)) + ((b.x + b.y) + (b.z + b.w))
           + ((c.x + c.y) + (c.z + c.w));
    }

    float qw, qx, qy, qz;
    exp_quat_dt(ux, uy, uz, qw, qx, qy, qz);      // qhat for group m

    // ---- ground-truth increment for group m ----
    float pw, px, py, pz;
    {
        float n2 = fmaf(d.x, d.x, fmaf(d.y, d.y, d.z * d.z));
        float th = sqrtf(n2);
        float s, c;
        __sincosf(0.5f * th, &s, &c);
        float k = (th > 1e-7f) ? __fdividef(s, th) : 0.5f;
        pw = c; px = k * d.x; py = k * d.y; pz = k * d.z;
    }

    // ---- 16-level term ----
    float s16 = (g >= 5) ? log_huber_q(qw, qx, qy, qz, pw, px, py, pz) : 0.0f;

    // ---- 32-level: partner group is lane^1 ----
    float qwP = __shfl_xor_sync(0xFFFFFFFFu, qw, 1);
    float qxP = __shfl_xor_sync(0xFFFFFFFFu, qx, 1);
    float qyP = __shfl_xor_sync(0xFFFFFFFFu, qy, 1);
    float qzP = __shfl_xor_sync(0xFFFFFFFFu, qz, 1);
    float pwP = __shfl_xor_sync(0xFFFFFFFFu, pw, 1);
    float pxP = __shfl_xor_sync(0xFFFFFFFFu, px, 1);
    float pyP = __shfl_xor_sync(0xFFFFFFFFu, py, 1);
    float pzP = __shfl_xor_sync(0xFFFFFFFFu, pz, 1);

    float s32 = 0.0f;
    if (mEven && g >= 10) {
        float hw, hx, hy, hz, gw, gx, gy, gz;
        qmul(qw, qx, qy, qz, qwP, qxP, qyP, qzP, hw, hx, hy, hz);   // hat pair
        qmul(pw, px, py, pz, pwP, pxP, pyP, pzP, gw, gx, gy, gz);   // gt pair
        s32 = log_huber_q(hw, hx, hy, hz, gw, gx, gy, gz);
    }

    // ---- deterministic block reduction ----
#pragma unroll
    for (int off = 16; off > 0; off >>= 1) {
        s16 += __shfl_down_sync(0xFFFFFFFFu, s16, off);
        s32 += __shfl_down_sync(0xFFFFFFFFu, s32, off);
    }
    __shared__ float w16[kThreads / 32], w32[kThreads / 32];
    __shared__ double sa[kThreads], sb[kThreads];
    __shared__ bool isLast;
    int lane = tid & 31, wid = tid >> 5;
    if (lane == 0) { w16[wid] = s16; w32[wid] = s32; }
    __syncthreads();
    if (tid == 0) {
        float a = 0.0f, b = 0.0f;
#pragma unroll
        for (int i = 0; i < kThreads / 32; i++) { a += w16[i]; b += w32[i]; }
        g_partials[blockIdx.x] = (double)a;
        g_partials[kBlocks + blockIdx.x] = (double)b;
        __threadfence();
        unsigned prev = atomicAdd(&g_sync, 1u);
        isLast = (prev == (unsigned)(kBlocks - 1));
    }
    __syncthreads();

    // ---- last block: fixed-order final sum => deterministic ----
    if (isLast) {
        __threadfence();
        int tt = tid;
        double a = 0.0, b = 0.0;
#pragma unroll
        for (int j = 0; j < kBlocks / kThreads; j++) {
            a += g_partials[tt + j * kThreads];
            b += g_partials[kBlocks + tt + j * kThreads];
        }
        sa[tt] = a; sb[tt] = b;
        __syncthreads();
        for (int off = kThreads / 2; off > 0; off >>= 1) {
            if (tt < off) { sa[tt] += sa[tt + off]; sb[tt] += sb[tt + off]; }
            __syncthreads();
        }
        if (tt == 0) {
            // W * HUBER^2 = 25;  loss16 denom 64*2043*3;  loss32 denom 64*1019*3*4
            double l16 = 25.0 * sa[0] / 392256.0;
            double l32 = 25.0 * sb[0] / 782592.0;
            out[0] = (float)(l16 + l32);
            g_sync = 0;                          // reset for next graph replay
        }
    }
}

extern "C" void kernel_launch(void* const* d_in, const int* in_sizes, int n_in,
                              void* d_out, int out_size) {
    const float* w_hat = (const float*)d_in[0];
    const float* dw16  = (const float*)d_in[1];
    float* out = (float*)d_out;
    dg_loss_kernel<<<kBlocks, kThreads>>>(w_hat, dw16, out);
}

// round 11
// speedup vs baseline: 1.1662x; 1.0286x over previous
#include <cuda_runtime.h>

namespace {
constexpr int kGroups   = 131072;                 // 64 * 2048
constexpr int kThreadsT = 2 * kGroups;            // 2 threads (halves) per group
constexpr int kThreads  = 256;
constexpr int kBlocks   = kThreadsT / kThreads;   // 1024
constexpr int kVecs     = kThreads * 6;           // 1536 float4 per block tile
constexpr float kDT = 0.005f;
}

// [0..kBlocks-1] = per-block sum16, [kBlocks..2*kBlocks-1] = sum32
__device__ double g_partials[2 * kBlocks];
__device__ unsigned int g_sync = 0;

__device__ __forceinline__ void qmul(float aw, float ax, float ay, float az,
                                     float bw, float bx, float by, float bz,
                                     float& w, float& x, float& y, float& z) {
    w = aw*bw - ax*bx - ay*by - az*bz;
    x = aw*bx + ax*bw + ay*bz - az*by;
    y = aw*by - ax*bz + ay*bw + az*bx;
    z = aw*bz + ax*by - ay*bx + az*bw;
}

// exp of phi = kDT * u as unit quaternion, |phi| <= ~0.2: even-poly, branch-free.
__device__ __forceinline__ void exp_quat_dt(float ux, float uy, float uz,
                                            float& w, float& x, float& y, float& z) {
    float n2 = fmaf(ux, ux, fmaf(uy, uy, uz * uz));
    float h2 = (0.25f * kDT * kDT) * n2;                    // (|phi|/2)^2
    w = fmaf(h2, fmaf(h2, (1.0f / 24.0f), -0.5f), 1.0f);
    float s = fmaf(h2, fmaf(h2, (kDT / 240.0f), -(kDT / 12.0f)), 0.5f * kDT);
    x = s * ux; y = s * uy; z = s * uz;                     // s = sin(h)/|u|
}

// atan2(n, w) for n >= 0, w >= 0 (result in [0, pi/2]); ~1e-7 rad
__device__ __forceinline__ float atan2_pos(float n, float w) {
    bool swap = n > w;
    float num = swap ? w : n;
    float den = swap ? n : w;
    float q  = __fdividef(num, den);              // [0, 1]
    float q2 = q * q;
    float p =                     -0.0040540580734172f;
    p = fmaf(p, q2,  0.0218612288251226f);
    p = fmaf(p, q2, -0.0559098861838105f);
    p = fmaf(p, q2,  0.0964200441046623f);
    p = fmaf(p, q2, -0.1390853351676372f);
    p = fmaf(p, q2,  0.1994653599057577f);
    p = fmaf(p, q2, -0.3332985605689738f);
    p = fmaf(p, q2,  0.9999993329093277f);
    float a = p * q;
    return swap ? (1.5707963267948966f - a) : a;
}

// rs = log( R(a)^T R(b) );  returns sum_k SmoothL1(rs_k / HUBER)
__device__ __forceinline__ float log_huber_q(float aw, float ax, float ay, float az,
                                             float bw, float bx, float by, float bz) {
    float w = aw*bw + ax*bx + ay*by + az*bz;      // conj(a) (x) b
    float x = aw*bx - ax*bw - ay*bz + az*by;
    float y = aw*by + ax*bz - ay*bw - az*bx;
    float z = aw*bz - ax*by + ay*bx - az*bw;
    if (w < 0.0f) { w = -w; x = -x; y = -y; z = -z; }
    float n2 = fmaf(x, x, fmaf(y, y, z * z));
    float n  = sqrtf(n2);
    float ang = 2.0f * atan2_pos(n, w);           // [0, pi]
    float coef = __fdividef(ang, fmaxf(n, 1e-20f));
    float r0 = coef * x, r1 = coef * y, r2 = coef * z;

    float sum = 0.0f;
#pragma unroll
    for (int k = 0; k < 3; k++) {
        float r = (k == 0) ? r0 : ((k == 1) ? r1 : r2);
        float xx = r * 200.0f;                    // / HUBER
        float axv = fabsf(xx);
        sum += (axv < 1.0f) ? (0.5f * xx * xx) : (axv - 0.5f);
    }
    return sum;
}

__global__ void __launch_bounds__(kThreads)
dg_loss_kernel(const float* __restrict__ w_hat, const float* __restrict__ dw16,
               float* __restrict__ out) {
    // component-separated BCH partials for this block's tile.
    // phase-1 stores stride-1 (no conflicts); phase-2 reads 6 contiguous floats
    // per half-group (3x LDS.64, 6-bank thread stride => conflict-free phases).
    __shared__ float s0[kVecs], s1[kVecs], s2[kVecs];

    const int tid  = threadIdx.x;
    const int t    = blockIdx.x * kThreads + tid;          // half-group id, 0..262143
    const int m    = t >> 1;                               // group id
    const int g    = m & 2047;                             // group index in row
    const int half = t & 1;
    const bool mEven = (m & 1) == 0;

    // ---- phase 1: fully coalesced w_hat load + per-float4 component partials ----
    // global float4 index jl: floats 4jl..4jl+3, component of float (4jl+l) = (jl+l) mod 3.
    const float4* wbase = reinterpret_cast<const float4*>(w_hat)
                        + (size_t)blockIdx.x * kVecs;      // kVecs % 3 == 0 -> local jl%3 valid
    // dw16 load issued early (latency overlap with phase 1)
    float4 d = __ldcs(reinterpret_cast<const float4*>(dw16) + (size_t)m * 12);

#pragma unroll
    for (int it = 0; it < 6; it++) {
        int jl = it * kThreads + tid;                      // 0..1535
        float4 v = __ldcs(wbase + jl);
        int r = jl % 3;
        float fs = v.x + v.w;                              // comps (r, r+1, r+2, r)
        float c0 = (r == 0) ? fs  : ((r == 1) ? v.z : v.y);
        float c1 = (r == 0) ? v.y : ((r == 1) ? fs  : v.z);
        float c2 = (r == 0) ? v.z : ((r == 1) ? v.y : fs );
        s0[jl] = c0; s1[jl] = c1; s2[jl] = c2;
    }
    __syncthreads();

    // ---- phase 2: this half-group's sum = 6 contiguous partials per component ----
    float ux, uy, uz;
    {
        const float2* p0 = reinterpret_cast<const float2*>(s0 + 6 * tid);
        const float2* p1 = reinterpret_cast<const float2*>(s1 + 6 * tid);
        const float2* p2 = reinterpret_cast<const float2*>(s2 + 6 * tid);
        float2 a = p0[0], b = p0[1], c = p0[2];
        ux = (a.x + a.y) + (b.x + b.y) + (c.x + c.y);
        a = p1[0]; b = p1[1]; c = p1[2];
        uy = (a.x + a.y) + (b.x + b.y) + (c.x + c.y);
        a = p2[0]; b = p2[1]; c = p2[2];
        uz = (a.x + a.y) + (b.x + b.y) + (c.x + c.y);
    }

    // ---- combine halves (BCH: vector sums add); both lanes identical ----
    ux += __shfl_xor_sync(0xFFFFFFFFu, ux, 1);
    uy += __shfl_xor_sync(0xFFFFFFFFu, uy, 1);
    uz += __shfl_xor_sync(0xFFFFFFFFu, uz, 1);

    float qw, qx, qy, qz;
    exp_quat_dt(ux, uy, uz, qw, qx, qy, qz);      // qhat for group m

    // ---- ground-truth increment for group m (both lanes, uniform) ----
    float pw, px, py, pz;
    {
        float n2 = fmaf(d.x, d.x, fmaf(d.y, d.y, d.z * d.z));
        float th = sqrtf(n2);
        float s, c;
        __sincosf(0.5f * th, &s, &c);
        float k = (th > 1e-7f) ? __fdividef(s, th) : 0.5f;
        pw = c; px = k * d.x; py = k * d.y; pz = k * d.z;
    }

    // ---- exchange with partner group (m ^ 1): lanes t <-> t^2 ----
    float qwP = __shfl_xor_sync(0xFFFFFFFFu, qw, 2);
    float qxP = __shfl_xor_sync(0xFFFFFFFFu, qx, 2);
    float qyP = __shfl_xor_sync(0xFFFFFFFFu, qy, 2);
    float qzP = __shfl_xor_sync(0xFFFFFFFFu, qz, 2);
    float pwP = __shfl_xor_sync(0xFFFFFFFFu, pw, 2);
    float pxP = __shfl_xor_sync(0xFFFFFFFFu, px, 2);
    float pyP = __shfl_xor_sync(0xFFFFFFFFu, py, 2);
    float pzP = __shfl_xor_sync(0xFFFFFFFFu, pz, 2);

    // ---- ONE log/huber pass, lane-specialized ----
    // half==0 lanes: 16-level (qhat_m vs gt_m)
    // half==1 lanes: 32-level pair (q_m (x) q_{m^1} vs gt_m (x) gt_{m^1})
    float Aw, Ax, Ay, Az, Bw, Bx, By, Bz;
    if (half == 0) {
        Aw = qw; Ax = qx; Ay = qy; Az = qz;
        Bw = pw; Bx = px; By = py; Bz = pz;
    } else {
        qmul(qw, qx, qy, qz, qwP, qxP, qyP, qzP, Aw, Ax, Ay, Az);  // hat pair
        qmul(pw, px, py, pz, pwP, pxP, pyP, pzP, Bw, Bx, By, Bz);  // gt pair
    }
    float val = log_huber_q(Aw, Ax, Ay, Az, Bw, Bx, By, Bz);

    float s16 = (half == 0 && g >= 5) ? val : 0.0f;
    float s32 = (half == 1 && mEven && g >= 10) ? val : 0.0f;

    // ---- deterministic block reduction ----
#pragma unroll
    for (int off = 16; off > 0; off >>= 1) {
        s16 += __shfl_down_sync(0xFFFFFFFFu, s16, off);
        s32 += __shfl_down_sync(0xFFFFFFFFu, s32, off);
    }
    __shared__ float w16[kThreads / 32], w32[kThreads / 32];
    __shared__ double sa[kThreads], sb[kThreads];
    __shared__ bool isLast;
    int lane = tid & 31, wid = tid >> 5;
    if (lane == 0) { w16[wid] = s16; w32[wid] = s32; }
    __syncthreads();
    if (tid == 0) {
        float a = 0.0f, b = 0.0f;
#pragma unroll
        for (int i = 0; i < kThreads / 32; i++) { a += w16[i]; b += w32[i]; }
        g_partials[blockIdx.x] = (double)a;
        g_partials[kBlocks + blockIdx.x] = (double)b;
        __threadfence();
        unsigned prev = atomicAdd(&g_sync, 1u);
        isLast = (prev == (unsigned)(kBlocks - 1));
    }
    __syncthreads();

    // ---- last block: fixed-order final sum => deterministic ----
    if (isLast) {
        __threadfence();
        int tt = tid;
        double a = 0.0, b = 0.0;
#pragma unroll
        for (int j = 0; j < kBlocks / kThreads; j++) {
            a += g_partials[tt + j * kThreads];
            b += g_partials[kBlocks + tt + j * kThreads];
        }
        sa[tt] = a; sb[tt] = b;
        __syncthreads();
        for (int off = kThreads / 2; off > 0; off >>= 1) {
            if (tt < off) { sa[tt] += sa[tt + off]; sb[tt] += sb[tt + off]; }
            __syncthreads();
        }
        if (tt == 0) {
            // W * HUBER^2 = 25;  loss16 denom 64*2043*3;  loss32 denom 64*1019*3*4
            double l16 = 25.0 * sa[0] / 392256.0;
            double l32 = 25.0 * sb[0] / 782592.0;
            out[0] = (float)(l16 + l32);
            g_sync = 0;                          // reset for next graph replay
        }
    }
}

extern "C" void kernel_launch(void* const* d_in, const int* in_sizes, int n_in,
                              void* d_out, int out_size) {
    const float* w_hat = (const float*)d_in[0];
    const float* dw16  = (const float*)d_in[1];
    float* out = (float*)d_out;
    dg_loss_kernel<<<kBlocks, kThreads>>>(w_hat, dw16, out);
}